// round 1
// baseline (speedup 1.0000x reference)
#include <cuda_runtime.h>
#include <math.h>

#define NN 1024
#define HH 64

// Scratch (device globals — no allocation allowed in kernel_launch)
__device__ float g_A[NN * HH];     // z_c @ W1[:64]
__device__ float g_B[NN * HH];     // z_d @ W1[64:] + b1
__device__ float g_T1[NN * NN];    // pairwise scores
__device__ float g_lse[NN];
__device__ float g_diag[NN];

// ---------------------------------------------------------------------------
// Kernel 1: precompute A and B.  grid (NN/4, 2), block 256.
// ---------------------------------------------------------------------------
__global__ void prep_kernel(const float* __restrict__ zc,
                            const float* __restrict__ zd,
                            const float* __restrict__ W1,
                            const float* __restrict__ b1) {
    int which = blockIdx.y;                      // 0 -> A, 1 -> B
    int row = blockIdx.x * 4 + (threadIdx.x >> 6);
    int col = threadIdx.x & 63;
    const float* src = which ? zd : zc;
    const float* w   = W1 + (which ? 64 * HH : 0);
    float s = which ? b1[col] : 0.0f;
#pragma unroll 8
    for (int k = 0; k < 64; ++k)
        s = fmaf(src[row * 64 + k], w[k * HH + col], s);
    if (which) g_B[row * HH + col] = s;
    else       g_A[row * HH + col] = s;
}

// ---------------------------------------------------------------------------
// Kernel 2: pairwise MLP.  16x16 pairs per CTA, one pair per thread.
// Packed f32x2 FMA (FFMA2) for 2x fp32 throughput on sm_103a.
// ---------------------------------------------------------------------------
#define FMA2(acc, a, b) \
    asm("fma.rn.f32x2 %0, %1, %2, %0;" : "+l"(acc) : "l"(a), "l"(b))

__global__ __launch_bounds__(256, 2) void pair_kernel(
    const float* __restrict__ W2, const float* __restrict__ b2,
    const float* __restrict__ Wo, const float* __restrict__ bo) {
    __shared__ __align__(16) float sW2[64][64];   // row k, col n (n contiguous)
    __shared__ float sA[16][65];
    __shared__ float sB[16][65];
    __shared__ float sb2[64], sWo[64];

    int tid = threadIdx.x;
    int j0 = blockIdx.x * 16;
    int i0 = blockIdx.y * 16;

    for (int t = tid; t < 4096; t += 256) sW2[t >> 6][t & 63] = W2[t];
    for (int t = tid; t < 1024; t += 256) {
        sA[t >> 6][t & 63] = g_A[(j0 + (t >> 6)) * 64 + (t & 63)];
        sB[t >> 6][t & 63] = g_B[(i0 + (t >> 6)) * 64 + (t & 63)];
    }
    if (tid < 64) { sb2[tid] = b2[tid]; sWo[tid] = Wo[tid]; }
    __syncthreads();

    int jl = tid & 15;
    int il = tid >> 4;

    unsigned long long acc[32];   // 64 fp32 accumulators packed as f32x2
#pragma unroll
    for (int n = 0; n < 32; ++n) acc[n] = 0ull;

#pragma unroll 8
    for (int k = 0; k < 64; ++k) {
        float h = fmaxf(sA[jl][k] + sB[il][k], 0.0f);   // relu(h1[k])
        unsigned long long hh;
        asm("mov.b64 %0, {%1, %1};" : "=l"(hh) : "f"(h));
        const ulonglong2* wrow =
            reinterpret_cast<const ulonglong2*>(&sW2[k][0]);  // broadcast LDS.128
#pragma unroll
        for (int n4 = 0; n4 < 16; ++n4) {
            ulonglong2 w = wrow[n4];
            FMA2(acc[2 * n4],     hh, w.x);
            FMA2(acc[2 * n4 + 1], hh, w.y);
        }
    }

    // Epilogue: relu(acc + b2) . Wo + bo
    float t1 = bo[0];
#pragma unroll
    for (int n2 = 0; n2 < 32; ++n2) {
        float lo = __uint_as_float((unsigned)(acc[n2]));
        float hi = __uint_as_float((unsigned)(acc[n2] >> 32));
        float a = fmaxf(lo + sb2[2 * n2],     0.0f);
        float b = fmaxf(hi + sb2[2 * n2 + 1], 0.0f);
        t1 = fmaf(a, sWo[2 * n2],     t1);
        t1 = fmaf(b, sWo[2 * n2 + 1], t1);
    }
    g_T1[(size_t)(i0 + il) * NN + (j0 + jl)] = t1;
}

// ---------------------------------------------------------------------------
// Kernel 3: per-row logsumexp over j + grab diagonal.  One block per row.
// ---------------------------------------------------------------------------
__global__ void lse_kernel() {
    __shared__ float red[256];
    int i = blockIdx.x, tid = threadIdx.x;
    const float* row = g_T1 + (size_t)i * NN;

    float m = -1e30f;
    for (int t = tid; t < NN; t += 256) m = fmaxf(m, row[t]);
    red[tid] = m; __syncthreads();
    for (int s = 128; s > 0; s >>= 1) {
        if (tid < s) red[tid] = fmaxf(red[tid], red[tid + s]);
        __syncthreads();
    }
    m = red[0]; __syncthreads();

    float sum = 0.0f;
    for (int t = tid; t < NN; t += 256) sum += expf(row[t] - m);
    red[tid] = sum; __syncthreads();
    for (int s = 128; s > 0; s >>= 1) {
        if (tid < s) red[tid] += red[tid + s];
        __syncthreads();
    }
    if (tid == 0) {
        g_lse[i]  = m + logf(red[0]);
        g_diag[i] = row[i];
    }
}

// ---------------------------------------------------------------------------
// Kernel 4: final deterministic reduction -> scalar lower bound.
// ---------------------------------------------------------------------------
__global__ void final_kernel(float* out) {
    __shared__ double rd[256], rl[256];
    int tid = threadIdx.x;
    double sd = 0.0, sl = 0.0;
    for (int t = tid; t < NN; t += 256) {
        sd += (double)g_diag[t];
        sl += (double)g_lse[t];
    }
    rd[tid] = sd; rl[tid] = sl; __syncthreads();
    for (int s = 128; s > 0; s >>= 1) {
        if (tid < s) { rd[tid] += rd[tid + s]; rl[tid] += rl[tid + s]; }
        __syncthreads();
    }
    if (tid == 0)
        out[0] = (float)(rd[0] / NN - (rl[0] / NN - log((double)NN)));
}

// ---------------------------------------------------------------------------
extern "C" void kernel_launch(void* const* d_in, const int* in_sizes, int n_in,
                              void* d_out, int out_size) {
    const float* z_c = (const float*)d_in[0];
    const float* z_d = (const float*)d_in[1];
    const float* W1  = (const float*)d_in[2];
    const float* b1  = (const float*)d_in[3];
    const float* W2  = (const float*)d_in[4];
    const float* b2  = (const float*)d_in[5];
    const float* Wo  = (const float*)d_in[6];
    const float* bo  = (const float*)d_in[7];
    float* out = (float*)d_out;

    prep_kernel<<<dim3(NN / 4, 2), 256>>>(z_c, z_d, W1, b1);
    pair_kernel<<<dim3(NN / 16, NN / 16), 256>>>(W2, b2, Wo, bo);
    lse_kernel<<<NN, 256>>>();
    final_kernel<<<1, 256>>>(out);
}

// round 3
// speedup vs baseline: 2.9442x; 2.9442x over previous
#include <cuda_runtime.h>
#include <cuda_fp16.h>
#include <math.h>
#include <stdint.h>

#define NN 1024
#define HH 64

__device__ float g_A[NN * HH];     // z_c @ W1[:64]
__device__ float g_B[NN * HH];     // z_d @ W1[64:] + b1
__device__ float g_T1[NN * NN];
__device__ float g_lse[NN];
__device__ float g_diag[NN];

// ---------------------------------------------------------------------------
// mma.sync m16n8k16 fp16 -> fp32  (baseline PTX, works on sm_103 target)
// ---------------------------------------------------------------------------
#define MMA16816(c, a0, a1, a2, a3, b0, b1)                                   \
    asm("mma.sync.aligned.m16n8k16.row.col.f32.f16.f16.f32 "                  \
        "{%0,%1,%2,%3}, {%4,%5,%6,%7}, {%8,%9}, {%0,%1,%2,%3};"               \
        : "+f"((c)[0]), "+f"((c)[1]), "+f"((c)[2]), "+f"((c)[3])              \
        : "r"(a0), "r"(a1), "r"(a2), "r"(a3), "r"(b0), "r"(b1))

// pack two fp32 -> half2 {x=e0, y=e1}
__device__ __forceinline__ uint32_t pack_h2(float e0, float e1) {
    uint32_t r;
    asm("cvt.rn.f16x2.f32 %0, %1, %2;" : "=r"(r) : "f"(e1), "f"(e0));
    return r;
}
__device__ __forceinline__ float hi_part(float x) {   // top 10 mantissa bits
    return __uint_as_float(__float_as_uint(x) & 0xFFFFE000u);
}

// ---------------------------------------------------------------------------
// Kernel 1: precompute A and B
// ---------------------------------------------------------------------------
__global__ void prep_kernel(const float* __restrict__ zc,
                            const float* __restrict__ zd,
                            const float* __restrict__ W1,
                            const float* __restrict__ b1) {
    int which = blockIdx.y;
    int row = blockIdx.x * 4 + (threadIdx.x >> 6);
    int col = threadIdx.x & 63;
    const float* src = which ? zd : zc;
    const float* w   = W1 + (which ? 64 * HH : 0);
    float s = which ? b1[col] : 0.0f;
#pragma unroll 8
    for (int k = 0; k < 64; ++k)
        s = fmaf(src[row * 64 + k], w[k * HH + col], s);
    if (which) g_B[row * HH + col] = s;
    else       g_A[row * HH + col] = s;
}

// ---------------------------------------------------------------------------
// Kernel 2: pairwise MLP via HMMA, split-fp16 3-term fp32 emulation.
// CTA = 128 threads (4 warps), owns one 64-row j-block; loops over i.
// Warp w handles rows m = w*16 .. +15 of the j-block (M=16 per warp).
// W2 fragments (hi+lo) preloaded into registers once (constant all tiles).
// NO barriers in the main loop.
// ---------------------------------------------------------------------------
#define JSTRIDE 18   // CTAs per j-block; grid = 16 * 18 = 288

__global__ __launch_bounds__(128, 2) void pair_mma_kernel(
    const float* __restrict__ W2, const float* __restrict__ b2,
    const float* __restrict__ Wo, const float* __restrict__ bo_p) {
    __shared__ float sAT[64 * 68];   // [k][m], stride 68 (conflict-free frag reads)

    const int tid  = threadIdx.x;
    const int lane = tid & 31;
    const int wid  = tid >> 5;
    const int gid  = lane >> 2;      // 0..7
    const int tid4 = lane & 3;       // 0..3

    const int jb = blockIdx.x / JSTRIDE;     // 0..15
    const int s0i = blockIdx.x % JSTRIDE;    // starting i
    const int j0 = jb * 64;

    // ---- stage A block transposed: sAT[k*68 + m] = g_A[(j0+m)*64 + k] ----
    for (int idx = tid; idx < 4096; idx += 128) {
        int m = idx >> 6, k = idx & 63;
        sAT[k * 68 + m] = g_A[(size_t)j0 * 64 + idx];
    }

    // ---- preload W2 fragments (hi/lo split) into registers ----
    uint32_t Bh[4][8][2], Bl[4][8][2];
#pragma unroll
    for (int ks = 0; ks < 4; ++ks) {
#pragma unroll
        for (int nt = 0; nt < 8; ++nt) {
            int k0 = 16 * ks + 2 * tid4;
            int n  = 8 * nt + gid;
            float w00 = W2[(k0 + 0) * HH + n], w01 = W2[(k0 + 1) * HH + n];
            float w10 = W2[(k0 + 8) * HH + n], w11 = W2[(k0 + 9) * HH + n];
            float h00 = hi_part(w00), h01 = hi_part(w01);
            float h10 = hi_part(w10), h11 = hi_part(w11);
            Bh[ks][nt][0] = pack_h2(h00, h01);
            Bh[ks][nt][1] = pack_h2(h10, h11);
            Bl[ks][nt][0] = pack_h2(w00 - h00, w01 - h01);
            Bl[ks][nt][1] = pack_h2(w10 - h10, w11 - h11);
        }
    }

    // ---- per-thread epilogue constants ----
    float2 b2r[8], wor[8];
#pragma unroll
    for (int nt = 0; nt < 8; ++nt) {
        int n = 8 * nt + 2 * tid4;
        b2r[nt] = make_float2(b2[n], b2[n + 1]);
        wor[nt] = make_float2(Wo[n], Wo[n + 1]);
    }
    const float bo = bo_p[0];

    const int m0 = wid * 16 + gid;   // this thread's first row in j-block

    __syncthreads();                 // sAT ready (only barrier in kernel)

    for (int i = s0i; i < NN; i += JSTRIDE) {
        const float* Bi = g_B + (size_t)i * 64;

        float acc[8][4];
#pragma unroll
        for (int nt = 0; nt < 8; ++nt)
#pragma unroll
            for (int q = 0; q < 4; ++q) acc[nt][q] = 0.0f;

#pragma unroll
        for (int ks = 0; ks < 4; ++ks) {
            const int k0 = 16 * ks + 2 * tid4;
            float2 biL = *(const float2*)(Bi + k0);       // k0, k0+1
            float2 biH = *(const float2*)(Bi + k0 + 8);   // k0+8, k0+9

            const float* cL = sAT + k0 * 68 + m0;         // row k0, col m0
            float h0 = fmaxf(cL[0]        + biL.x, 0.f);  // (m0,   k0)
            float h1 = fmaxf(cL[68]       + biL.y, 0.f);  // (m0,   k0+1)
            float h2 = fmaxf(cL[8 * 68]   + biH.x, 0.f);  // (m0,   k0+8)
            float h3 = fmaxf(cL[9 * 68]   + biH.y, 0.f);  // (m0,   k0+9)
            float h4 = fmaxf(cL[8]        + biL.x, 0.f);  // (m0+8, k0)
            float h5 = fmaxf(cL[68 + 8]   + biL.y, 0.f);
            float h6 = fmaxf(cL[8*68 + 8] + biH.x, 0.f);
            float h7 = fmaxf(cL[9*68 + 8] + biH.y, 0.f);

            float g0 = hi_part(h0), g1 = hi_part(h1), g2 = hi_part(h2),
                  g3 = hi_part(h3), g4 = hi_part(h4), g5 = hi_part(h5),
                  g6 = hi_part(h6), g7 = hi_part(h7);

            uint32_t a0h = pack_h2(g0, g1);
            uint32_t a1h = pack_h2(g4, g5);
            uint32_t a2h = pack_h2(g2, g3);
            uint32_t a3h = pack_h2(g6, g7);
            uint32_t a0l = pack_h2(h0 - g0, h1 - g1);
            uint32_t a1l = pack_h2(h4 - g4, h5 - g5);
            uint32_t a2l = pack_h2(h2 - g2, h3 - g3);
            uint32_t a3l = pack_h2(h6 - g6, h7 - g7);

#pragma unroll
            for (int nt = 0; nt < 8; ++nt) {
                MMA16816(acc[nt], a0h, a1h, a2h, a3h,
                         Bh[ks][nt][0], Bh[ks][nt][1]);
                MMA16816(acc[nt], a0h, a1h, a2h, a3h,
                         Bl[ks][nt][0], Bl[ks][nt][1]);
                MMA16816(acc[nt], a0l, a1l, a2l, a3l,
                         Bh[ks][nt][0], Bh[ks][nt][1]);
            }
        }

        // epilogue: rows m0 (c0,c1) and m0+8 (c2,c3)
        float sA0 = 0.f, sA1 = 0.f;
#pragma unroll
        for (int nt = 0; nt < 8; ++nt) {
            sA0 = fmaf(fmaxf(acc[nt][0] + b2r[nt].x, 0.f), wor[nt].x, sA0);
            sA0 = fmaf(fmaxf(acc[nt][1] + b2r[nt].y, 0.f), wor[nt].y, sA0);
            sA1 = fmaf(fmaxf(acc[nt][2] + b2r[nt].x, 0.f), wor[nt].x, sA1);
            sA1 = fmaf(fmaxf(acc[nt][3] + b2r[nt].y, 0.f), wor[nt].y, sA1);
        }
        sA0 += __shfl_xor_sync(0xffffffffu, sA0, 1);
        sA0 += __shfl_xor_sync(0xffffffffu, sA0, 2);
        sA1 += __shfl_xor_sync(0xffffffffu, sA1, 1);
        sA1 += __shfl_xor_sync(0xffffffffu, sA1, 2);
        if (tid4 == 0) {
            g_T1[(size_t)i * NN + j0 + m0]     = sA0 + bo;
            g_T1[(size_t)i * NN + j0 + m0 + 8] = sA1 + bo;
        }
    }
}

// ---------------------------------------------------------------------------
// Kernel 3: per-row logsumexp + diagonal
// ---------------------------------------------------------------------------
__global__ void lse_kernel() {
    __shared__ float red[256];
    int i = blockIdx.x, tid = threadIdx.x;
    const float* row = g_T1 + (size_t)i * NN;

    float m = -1e30f;
    for (int t = tid; t < NN; t += 256) m = fmaxf(m, row[t]);
    red[tid] = m; __syncthreads();
    for (int s = 128; s > 0; s >>= 1) {
        if (tid < s) red[tid] = fmaxf(red[tid], red[tid + s]);
        __syncthreads();
    }
    m = red[0]; __syncthreads();

    float sum = 0.0f;
    for (int t = tid; t < NN; t += 256) sum += expf(row[t] - m);
    red[tid] = sum; __syncthreads();
    for (int s = 128; s > 0; s >>= 1) {
        if (tid < s) red[tid] += red[tid + s];
        __syncthreads();
    }
    if (tid == 0) {
        g_lse[i]  = m + logf(red[0]);
        g_diag[i] = row[i];
    }
}

// ---------------------------------------------------------------------------
// Kernel 4: final reduction
// ---------------------------------------------------------------------------
__global__ void final_kernel(float* out) {
    __shared__ double red[32];
    int tid = threadIdx.x;
    double v = (double)g_diag[tid] - (double)g_lse[tid];
#pragma unroll
    for (int o = 16; o > 0; o >>= 1) v += __shfl_down_sync(0xffffffffu, v, o);
    if ((tid & 31) == 0) red[tid >> 5] = v;
    __syncthreads();
    if (tid < 32) {
        v = red[tid];
#pragma unroll
        for (int o = 16; o > 0; o >>= 1) v += __shfl_down_sync(0xffffffffu, v, o);
        if (tid == 0) out[0] = (float)(v / NN + log((double)NN));
    }
}

// ---------------------------------------------------------------------------
extern "C" void kernel_launch(void* const* d_in, const int* in_sizes, int n_in,
                              void* d_out, int out_size) {
    const float* z_c = (const float*)d_in[0];
    const float* z_d = (const float*)d_in[1];
    const float* W1  = (const float*)d_in[2];
    const float* b1  = (const float*)d_in[3];
    const float* W2  = (const float*)d_in[4];
    const float* b2  = (const float*)d_in[5];
    const float* Wo  = (const float*)d_in[6];
    const float* bo  = (const float*)d_in[7];
    float* out = (float*)d_out;

    prep_kernel<<<dim3(NN / 4, 2), 256>>>(z_c, z_d, W1, b1);
    pair_mma_kernel<<<16 * JSTRIDE, 128>>>(W2, b2, Wo, bo);
    lse_kernel<<<NN, 256>>>();
    final_kernel<<<1, 1024>>>(out);
}